// round 2
// baseline (speedup 1.0000x reference)
#include <cuda_runtime.h>

// ---------------------------------------------------------------------------
// OTPE single timestep.
// Inputs (metadata order): x[8192], W[8192,4096], u[4096], E[8192,4096],
//                          R_hat[8192,4096], g_bar[4096], ratio[1]
// Output (flattened tuple): s[4096], u_new[4096], E_new[8192*4096],
//                           R_new[8192*4096], g_bar_new[4096], ratio_new[1]
// ---------------------------------------------------------------------------

#define N_IN   8192
#define N_OUT  4096
#define N_OUTV (N_OUT / 4)               // 1024 float4 per row
// sigmoid(2.0) in fp32
#define SIG_TAU 0.88079707797788231f

#define NSPLIT 128
#define ROWS_PER_SPLIT (N_IN / NSPLIT)   // 64

// scratch (device globals; no allocation allowed)
__device__ __align__(16) float g_part[NSPLIT * N_OUT];   // 2 MB
__device__ __align__(16) float g_sg[N_OUT];

// ---------------------------------------------------------------------------
// K1: split-K GEMV partials, float4-vectorized over columns.
// grid (8, 128), block 128. Each thread owns 4 adjacent output columns
// within one 64-row split. 4 float4 loads batched per unroll step for MLP.
// ---------------------------------------------------------------------------
__global__ void __launch_bounds__(128)
otpe_gemv_partial(const float4* __restrict__ W4, const float* __restrict__ x) {
    __shared__ float sx[ROWS_PER_SPLIT];
    const int colv  = blockIdx.x * 128 + threadIdx.x;   // 0..1023
    const int split = blockIdx.y;
    const int r0    = split * ROWS_PER_SPLIT;

    if (threadIdx.x < ROWS_PER_SPLIT)
        sx[threadIdx.x] = x[r0 + threadIdx.x];
    __syncthreads();

    const float4* Wp = W4 + (size_t)r0 * N_OUTV + colv;

    float4 a0 = make_float4(0.f, 0.f, 0.f, 0.f);
    float4 a1 = make_float4(0.f, 0.f, 0.f, 0.f);

#pragma unroll 4
    for (int r = 0; r < ROWS_PER_SPLIT; r += 4) {
        // batch loads first -> 4 LDG.128 in flight per iteration
        const float4 w0 = Wp[(size_t)(r + 0) * N_OUTV];
        const float4 w1 = Wp[(size_t)(r + 1) * N_OUTV];
        const float4 w2 = Wp[(size_t)(r + 2) * N_OUTV];
        const float4 w3 = Wp[(size_t)(r + 3) * N_OUTV];
        const float x0 = sx[r + 0], x1 = sx[r + 1];
        const float x2 = sx[r + 2], x3 = sx[r + 3];

        a0.x = fmaf(x0, w0.x, a0.x); a0.y = fmaf(x0, w0.y, a0.y);
        a0.z = fmaf(x0, w0.z, a0.z); a0.w = fmaf(x0, w0.w, a0.w);
        a1.x = fmaf(x1, w1.x, a1.x); a1.y = fmaf(x1, w1.y, a1.y);
        a1.z = fmaf(x1, w1.z, a1.z); a1.w = fmaf(x1, w1.w, a1.w);
        a0.x = fmaf(x2, w2.x, a0.x); a0.y = fmaf(x2, w2.y, a0.y);
        a0.z = fmaf(x2, w2.z, a0.z); a0.w = fmaf(x2, w2.w, a0.w);
        a1.x = fmaf(x3, w3.x, a1.x); a1.y = fmaf(x3, w3.y, a1.y);
        a1.z = fmaf(x3, w3.z, a1.z); a1.w = fmaf(x3, w3.w, a1.w);
    }

    float4 out;
    out.x = a0.x + a1.x; out.y = a0.y + a1.y;
    out.z = a0.z + a1.z; out.w = a0.w + a1.w;
    reinterpret_cast<float4*>(g_part)[split * N_OUTV + colv] = out;
}

// ---------------------------------------------------------------------------
// K2: deterministic reduce over 128 splits + per-column post.
// grid 32, block 128 (4096 threads). Partials are L2-resident.
// ---------------------------------------------------------------------------
__global__ void __launch_bounds__(128)
otpe_column_post(const float* __restrict__ u,
                 const float* __restrict__ g_bar,
                 const float* __restrict__ ratio,
                 float* __restrict__ out_s,
                 float* __restrict__ out_u,
                 float* __restrict__ out_gbar,
                 float* __restrict__ out_ratio) {
    const int j = blockIdx.x * 128 + threadIdx.x;

    float a0 = SIG_TAU * u[j], a1 = 0.f, a2 = 0.f, a3 = 0.f;
#pragma unroll 8
    for (int s = 0; s < NSPLIT; s += 4) {
        a0 += g_part[(s + 0) * N_OUT + j];
        a1 += g_part[(s + 1) * N_OUT + j];
        a2 += g_part[(s + 2) * N_OUT + j];
        a3 += g_part[(s + 3) * N_OUT + j];
    }
    const float u_pre = (a0 + a1) + (a2 + a3);

    const float spike = (u_pre >= 1.0f) ? 1.0f : 0.0f;
    const float t  = fmaf(10.0f, fabsf(u_pre - 1.0f), 1.0f);
    const float sg = 1.0f / (t * t);

    g_sg[j]  = sg;
    out_s[j] = spike;
    out_u[j] = u_pre - spike;          // soft reset (V_TH = 1)

    const float r0        = SIG_TAU * ratio[0];
    const float ratio_new = r0 + 1.0f;
    const float r         = r0 / ratio_new;
    // ds_du_prev / sig_tau == sg
    out_gbar[j] = fmaf(r, g_bar[j], (1.0f - r) * sg);

    if (j == 0) out_ratio[0] = ratio_new;
}

// ---------------------------------------------------------------------------
// K3: fused E/R update, float4 vectorized. Reads old E once; serves both
// E_new and the sg*sig*E term of R_new. grid 32768, block 256.
// ---------------------------------------------------------------------------
__global__ void __launch_bounds__(256)
otpe_big_elem(const float4* __restrict__ E,
              const float4* __restrict__ R,
              const float*  __restrict__ x,
              float4* __restrict__ Eo,
              float4* __restrict__ Ro) {
    const long long v = (long long)blockIdx.x * 256 + threadIdx.x;
    const int row  = (int)(v >> 10);        // 1024 float4 per row
    const int colv = (int)(v & 1023);

    const float  xi  = __ldg(&x[row]);
    const float4 sg4 = reinterpret_cast<const float4*>(g_sg)[colv];
    const float4 e   = E[v];
    const float4 rr  = R[v];

    float4 eo, ro;
    eo.x = fmaf(SIG_TAU, e.x, xi);
    eo.y = fmaf(SIG_TAU, e.y, xi);
    eo.z = fmaf(SIG_TAU, e.z, xi);
    eo.w = fmaf(SIG_TAU, e.w, xi);

    // R_new = sig*R + (sg*sig)*E_old + x*sg
    ro.x = fmaf(SIG_TAU, rr.x, fmaf(sg4.x * SIG_TAU, e.x, xi * sg4.x));
    ro.y = fmaf(SIG_TAU, rr.y, fmaf(sg4.y * SIG_TAU, e.y, xi * sg4.y));
    ro.z = fmaf(SIG_TAU, rr.z, fmaf(sg4.z * SIG_TAU, e.z, xi * sg4.z));
    ro.w = fmaf(SIG_TAU, rr.w, fmaf(sg4.w * SIG_TAU, e.w, xi * sg4.w));

    Eo[v] = eo;
    Ro[v] = ro;
}

// ---------------------------------------------------------------------------
extern "C" void kernel_launch(void* const* d_in, const int* in_sizes, int n_in,
                              void* d_out, int out_size) {
    const float* x     = (const float*)d_in[0];
    const float* W     = (const float*)d_in[1];
    const float* u     = (const float*)d_in[2];
    const float* E     = (const float*)d_in[3];
    const float* R     = (const float*)d_in[4];
    const float* g_bar = (const float*)d_in[5];
    const float* ratio = (const float*)d_in[6];

    float* out       = (float*)d_out;
    float* out_s     = out;
    float* out_u     = out + N_OUT;
    float* out_E     = out + 2 * N_OUT;
    float* out_R     = out_E + (size_t)N_IN * N_OUT;
    float* out_gbar  = out_R + (size_t)N_IN * N_OUT;
    float* out_ratio = out_gbar + N_OUT;

    otpe_gemv_partial<<<dim3(N_OUTV / 128, NSPLIT), 128>>>((const float4*)W, x);
    otpe_column_post<<<N_OUT / 128, 128>>>(u, g_bar, ratio,
                                           out_s, out_u, out_gbar, out_ratio);

    const long long nvec = (long long)N_IN * N_OUT / 4;   // 8388608
    otpe_big_elem<<<(unsigned)(nvec / 256), 256>>>(
        (const float4*)E, (const float4*)R, x,
        (float4*)out_E, (float4*)out_R);
}